// round 2
// baseline (speedup 1.0000x reference)
#include <cuda_runtime.h>
#include <math.h>

// Problem constants
static constexpr int BB  = 4096;
static constexpr int D3  = 288;
static constexpr int LZ  = 32;
static constexpr int HH  = 512;
static constexpr int OO  = 96;
static constexpr int EE  = 8;
static constexpr int GHD = 128;

static constexpr int IN0 = D3 + LZ;   // 320
static constexpr int IN1 = HH + LZ;   // 544

// Scratch (no allocations allowed -> __device__ globals)
__device__ float d_hcat0[BB * IN0];
__device__ float d_hcat1[BB * IN1];
__device__ float d_hcat2[BB * IN1];
__device__ float d_h3[BB * HH];
__device__ float d_gh1[BB * GHD];
__device__ float d_gh2[BB * GHD];
__device__ float d_gate[BB * EE];

// ---- packed fp32x2 helpers (sm_103a: FFMA-3reg is half-rate; f32x2 restores full rate) ----
__device__ __forceinline__ void fma2(unsigned long long& d, unsigned long long a, unsigned long long b) {
    asm("fma.rn.f32x2 %0, %1, %2, %0;" : "+l"(d) : "l"(a), "l"(b));
}
__device__ __forceinline__ unsigned long long pack2(float lo, float hi) {
    unsigned long long r;
    asm("mov.b64 %0, {%1, %2};" : "=l"(r) : "f"(lo), "f"(hi));
    return r;
}
__device__ __forceinline__ float2 unpack2(unsigned long long v) {
    float2 f;
    asm("mov.b64 {%0, %1}, %2;" : "=f"(f.x), "=f"(f.y) : "l"(v));
    return f;
}
__device__ __forceinline__ float elu1(float x) { return x > 0.f ? x : expm1f(x); }

// ---- input packing: hcat0 = [x|z], and write z tails of hcat1/hcat2 once ----
__global__ void pack_kernel(const float* __restrict__ x, const float* __restrict__ z) {
    int idx = blockIdx.x * blockDim.x + threadIdx.x;
    if (idx < BB * IN0) {
        int b = idx / IN0, c = idx % IN0;
        d_hcat0[idx] = (c < D3) ? x[b * D3 + c] : z[b * LZ + (c - D3)];
    }
    if (idx < BB * LZ) {
        int b = idx / LZ;
        int c = idx % LZ;
        float zv = z[idx];
        d_hcat1[b * IN1 + HH + c] = zv;
        d_hcat2[b * IN1 + HH + c] = zv;
    }
}

// ---- blended expert GEMM ----
// C[b,o] = act( sum_e g[b,e] * ( sum_i A[b,i] * W[e,o,i] + bias[e,o] ) )
// GATE=false => E==1 plain linear with bias.
// Tiling: BM x 64 output tile, BK=16, 256 threads, thread tile TM x 4.
// M-dim paired into f32x2; W stored in smem pre-duplicated {w,w}.
template <int BM, int E, bool GATE, bool ACT>
__global__ void __launch_bounds__(256, 2) blended_gemm(
    const float* __restrict__ A, int lda,
    const float* __restrict__ W, const float* __restrict__ bias,
    const float* __restrict__ g,
    float* __restrict__ C, int ldc, int Nout, int Kin)
{
    constexpr int BN = 64, BK = 16;
    constexpr int TM  = BM / 16;   // 8 (BM=128) or 4 (BM=64)
    constexpr int TM2 = TM / 2;
    constexpr int TN  = 4;

    extern __shared__ char smraw[];
    float* As = (float*)smraw;                                             // [BK][BM]
    unsigned long long* Bs = (unsigned long long*)(smraw + BK * BM * 4);   // [E][BK][BN], dup pairs
    float* Gs = (float*)(smraw + BK * BM * 4 + (size_t)E * BK * BN * 8);   // [BM][E] (GATE only)

    const int tid = threadIdx.x;
    const int tx = tid & 15;
    const int ty = tid >> 4;
    const int m0 = blockIdx.y * BM;
    const int n0 = blockIdx.x * BN;
    const int mb = ty * TM;
    const int nb = tx * TN;

    if (GATE) {
        for (int i = tid; i < BM * E / 4; i += 256)
            ((float4*)Gs)[i] = ((const float4*)(g + (size_t)m0 * E))[i];
    }

    unsigned long long acc[TM2][TN];
#pragma unroll
    for (int i = 0; i < TM2; i++)
#pragma unroll
        for (int j = 0; j < TN; j++) acc[i][j] = 0ull;

    const int ktiles = Kin / BK;
    for (int kt = 0; kt < ktiles; kt++) {
        const int k0 = kt * BK;
        __syncthreads();
        // stage A tile (transposed to [k][m])
        for (int i = tid; i < BM * 4; i += 256) {
            int r = i >> 2, c4 = i & 3;
            float4 v = *(const float4*)(A + (size_t)(m0 + r) * lda + k0 + c4 * 4);
            int kk = c4 * 4;
            As[(kk + 0) * BM + r] = v.x;
            As[(kk + 1) * BM + r] = v.y;
            As[(kk + 2) * BM + r] = v.z;
            As[(kk + 3) * BM + r] = v.w;
        }
        // stage W tile, duplicated into 64-bit {w,w} pairs
        for (int i = tid; i < E * 256; i += 256) {
            int e = i >> 8;
            int rem = i & 255;
            int n = rem >> 2, c4 = rem & 3;
            float4 v = make_float4(0.f, 0.f, 0.f, 0.f);
            if (n0 + n < Nout)
                v = *(const float4*)(W + ((size_t)e * Nout + n0 + n) * Kin + k0 + c4 * 4);
            int kk = c4 * 4;
            unsigned long long* bp = Bs + ((size_t)e * BK) * BN + n;
            bp[(kk + 0) * BN] = pack2(v.x, v.x);
            bp[(kk + 1) * BN] = pack2(v.y, v.y);
            bp[(kk + 2) * BN] = pack2(v.z, v.z);
            bp[(kk + 3) * BN] = pack2(v.w, v.w);
        }
        __syncthreads();

#pragma unroll 1
        for (int e = 0; e < E; e++) {
            if (GATE) {
                unsigned long long part[TM2][TN];
#pragma unroll
                for (int i = 0; i < TM2; i++)
#pragma unroll
                    for (int j = 0; j < TN; j++) part[i][j] = 0ull;
#pragma unroll
                for (int k = 0; k < BK; k++) {
                    unsigned long long areg[TM2];
#pragma unroll
                    for (int i = 0; i < TM2 / 2; i++) {
                        ulonglong2 t = *(const ulonglong2*)(As + k * BM + mb + i * 4);
                        areg[2 * i]     = t.x;
                        areg[2 * i + 1] = t.y;
                    }
                    unsigned long long breg[TN];
#pragma unroll
                    for (int j = 0; j < TN / 2; j++) {
                        ulonglong2 t = *(const ulonglong2*)(Bs + ((size_t)e * BK + k) * BN + nb + j * 2);
                        breg[2 * j]     = t.x;
                        breg[2 * j + 1] = t.y;
                    }
#pragma unroll
                    for (int i = 0; i < TM2; i++)
#pragma unroll
                        for (int j = 0; j < TN; j++) fma2(part[i][j], areg[i], breg[j]);
                }
                // acc += g[b,e] * part   (per-row gate packed per M-pair)
#pragma unroll
                for (int i = 0; i < TM2; i++) {
                    unsigned long long gg =
                        pack2(Gs[(mb + 2 * i) * E + e], Gs[(mb + 2 * i + 1) * E + e]);
#pragma unroll
                    for (int j = 0; j < TN; j++) fma2(acc[i][j], gg, part[i][j]);
                }
            } else {
#pragma unroll
                for (int k = 0; k < BK; k++) {
                    unsigned long long areg[TM2];
#pragma unroll
                    for (int i = 0; i < TM2 / 2; i++) {
                        ulonglong2 t = *(const ulonglong2*)(As + k * BM + mb + i * 4);
                        areg[2 * i]     = t.x;
                        areg[2 * i + 1] = t.y;
                    }
                    unsigned long long breg[TN];
#pragma unroll
                    for (int j = 0; j < TN / 2; j++) {
                        ulonglong2 t = *(const ulonglong2*)(Bs + ((size_t)e * BK + k) * BN + nb + j * 2);
                        breg[2 * j]     = t.x;
                        breg[2 * j + 1] = t.y;
                    }
#pragma unroll
                    for (int i = 0; i < TM2; i++)
#pragma unroll
                        for (int j = 0; j < TN; j++) fma2(acc[i][j], areg[i], breg[j]);
                }
            }
        }
    }

    // epilogue: blended bias + activation
#pragma unroll
    for (int i = 0; i < TM2; i++) {
        int r0 = m0 + mb + 2 * i;
#pragma unroll
        for (int j = 0; j < TN; j++) {
            int o = n0 + nb + j;
            if (o < Nout) {
                float2 v = unpack2(acc[i][j]);
                if (GATE) {
                    float s0 = 0.f, s1 = 0.f;
#pragma unroll
                    for (int e = 0; e < E; e++) {
                        float bb = bias[e * Nout + o];
                        s0 += Gs[(mb + 2 * i) * E + e] * bb;
                        s1 += Gs[(mb + 2 * i + 1) * E + e] * bb;
                    }
                    v.x += s0; v.y += s1;
                } else {
                    float bb = bias[o];
                    v.x += bb; v.y += bb;
                }
                if (ACT) { v.x = elu1(v.x); v.y = elu1(v.y); }
                C[(size_t)r0 * ldc + o]       = v.x;
                C[(size_t)(r0 + 1) * ldc + o] = v.y;
            }
        }
    }
}

// ---- gating logits + softmax over E=8 (one thread per (row, expert)) ----
__global__ void logits_softmax(const float* __restrict__ h2,
                               const float* __restrict__ gW3,
                               const float* __restrict__ gb3) {
    int tid = blockIdx.x * blockDim.x + threadIdx.x;
    int row = tid >> 3;
    int e = tid & 7;
    if (row >= BB) return;
    float s = gb3[e];
    const float* hr = h2 + (size_t)row * GHD;
    const float* wr = gW3 + (size_t)e * GHD;
#pragma unroll 8
    for (int i = 0; i < GHD; i++) s += hr[i] * wr[i];
    // softmax within groups of 8 lanes (shfl_xor 1/2/4 stays in group)
    float m = s;
#pragma unroll
    for (int o = 4; o; o >>= 1) m = fmaxf(m, __shfl_xor_sync(0xffffffffu, m, o));
    float ex = expf(s - m);
    float sum = ex;
#pragma unroll
    for (int o = 4; o; o >>= 1) sum += __shfl_xor_sync(0xffffffffu, sum, o);
    d_gate[tid] = ex / sum;
}

extern "C" void kernel_launch(void* const* d_in, const int* in_sizes, int n_in,
                              void* d_out, int out_size) {
    const float* x   = (const float*)d_in[0];
    const float* z   = (const float*)d_in[1];
    const float* W0  = (const float*)d_in[2];
    const float* b0  = (const float*)d_in[3];
    const float* W1  = (const float*)d_in[4];
    const float* b1  = (const float*)d_in[5];
    const float* W2  = (const float*)d_in[6];
    const float* b2  = (const float*)d_in[7];
    const float* W3  = (const float*)d_in[8];
    const float* b3  = (const float*)d_in[9];
    const float* gW1 = (const float*)d_in[10];
    const float* gb1 = (const float*)d_in[11];
    const float* gW2 = (const float*)d_in[12];
    const float* gb2 = (const float*)d_in[13];
    const float* gW3 = (const float*)d_in[14];
    const float* gb3 = (const float*)d_in[15];
    float* out = (float*)d_out;
    (void)in_sizes; (void)n_in; (void)out_size;

    float *hcat0, *hcat1, *hcat2, *h3, *gh1, *gh2, *gate;
    cudaGetSymbolAddress((void**)&hcat0, d_hcat0);
    cudaGetSymbolAddress((void**)&hcat1, d_hcat1);
    cudaGetSymbolAddress((void**)&hcat2, d_hcat2);
    cudaGetSymbolAddress((void**)&h3,    d_h3);
    cudaGetSymbolAddress((void**)&gh1,   d_gh1);
    cudaGetSymbolAddress((void**)&gh2,   d_gh2);
    cudaGetSymbolAddress((void**)&gate,  d_gate);

    // dynamic smem sizes
    constexpr int SM_128_8 = 16 * 128 * 4 + 8 * 16 * 64 * 8 + 128 * 8 * 4;  // 77824
    constexpr int SM_64_8  = 16 * 64 * 4  + 8 * 16 * 64 * 8 + 64 * 8 * 4;   // 71680
    constexpr int SM_128_1 = 16 * 128 * 4 + 1 * 16 * 64 * 8;                // 16384

    cudaFuncSetAttribute(blended_gemm<128, 8, true, true>,
                         cudaFuncAttributeMaxDynamicSharedMemorySize, SM_128_8);
    cudaFuncSetAttribute(blended_gemm<64, 8, true, false>,
                         cudaFuncAttributeMaxDynamicSharedMemorySize, SM_64_8);

    // 1. pack [x|z] and z-tails
    pack_kernel<<<(BB * IN0 + 255) / 256, 256>>>(x, z);

    // 2. gating MLP
    blended_gemm<128, 1, false, true><<<dim3(2, 32), 256, SM_128_1>>>(
        hcat0, IN0, gW1, gb1, nullptr, gh1, GHD, GHD, IN0);
    blended_gemm<128, 1, false, true><<<dim3(2, 32), 256, SM_128_1>>>(
        gh1, GHD, gW2, gb2, nullptr, gh2, GHD, GHD, GHD);
    logits_softmax<<<BB * EE / 256, 256>>>(gh2, gW3, gb3);

    // 3. blended expert layers
    blended_gemm<128, 8, true, true><<<dim3(8, 32), 256, SM_128_8>>>(
        hcat0, IN0, W0, b0, gate, hcat1, IN1, HH, IN0);
    blended_gemm<128, 8, true, true><<<dim3(8, 32), 256, SM_128_8>>>(
        hcat1, IN1, W1, b1, gate, hcat2, IN1, HH, IN1);
    blended_gemm<128, 8, true, true><<<dim3(8, 32), 256, SM_128_8>>>(
        hcat2, IN1, W2, b2, gate, h3, HH, HH, IN1);
    blended_gemm<64, 8, true, false><<<dim3(2, 64), 256, SM_64_8>>>(
        h3, HH, W3, b3, gate, out, OO, OO, HH);
}